// round 1
// baseline (speedup 1.0000x reference)
#include <cuda_runtime.h>

#define BB   16
#define CIN  512
#define COUT 512
#define HH   64
#define WW   64
#define WDIM 512

// Scratch (static device arrays — no allocation in kernel_launch)
__device__ float g_style[BB * CIN];            // style[b][i]
__device__ float g_wsumsq[COUT * CIN];         // sum over 3x3 of conv_w^2, [o][i]
__device__ float g_rnorm[BB * COUT];           // 1/norm per (b,o)
__device__ float g_wmod[(size_t)BB * CIN * 9 * COUT];  // [b][ic][k][oc], oc fastest

// ---------------------------------------------------------------------------
// K1: style[b][i] = dot(w_embs[b,:], style_w[i,:]) + style_b[i] + 1
// ---------------------------------------------------------------------------
__global__ void style_kernel(const float* __restrict__ w_embs,
                             const float* __restrict__ style_w,
                             const float* __restrict__ style_b) {
    __shared__ float se[WDIM];
    int b = blockIdx.x;
    for (int k = threadIdx.x; k < WDIM; k += blockDim.x)
        se[k] = w_embs[b * WDIM + k];
    __syncthreads();
    for (int i = threadIdx.x; i < CIN; i += blockDim.x) {
        const float* sr = style_w + (size_t)i * WDIM;
        float s = 0.f;
        #pragma unroll 8
        for (int k = 0; k < WDIM; k++) s += se[k] * sr[k];
        g_style[b * CIN + i] = s + style_b[i] + 1.0f;
    }
}

// ---------------------------------------------------------------------------
// K2a: wsumsq[o][i] = sum_{k in 3x3} conv_w[o][i][k]^2
// ---------------------------------------------------------------------------
__global__ void wsumsq_kernel(const float* __restrict__ conv_w) {
    int idx = blockIdx.x * blockDim.x + threadIdx.x;  // o*512 + i
    if (idx < COUT * CIN) {
        const float* p = conv_w + (size_t)idx * 9;
        float s = 0.f;
        #pragma unroll
        for (int k = 0; k < 9; k++) s += p[k] * p[k];
        g_wsumsq[idx] = s;
    }
}

// ---------------------------------------------------------------------------
// K2b: rnorm[b][o] = 1/sqrt(sum_i style[b,i]^2 * wsumsq[o][i])
// ---------------------------------------------------------------------------
__global__ void rnorm_kernel() {
    __shared__ float s2[CIN];
    int b = blockIdx.x;
    for (int i = threadIdx.x; i < CIN; i += blockDim.x) {
        float s = g_style[b * CIN + i];
        s2[i] = s * s;
    }
    __syncthreads();
    for (int o = threadIdx.x; o < COUT; o += blockDim.x) {
        const float* wr = g_wsumsq + (size_t)o * CIN;
        float sum = 0.f;
        #pragma unroll 8
        for (int i = 0; i < CIN; i++) sum += s2[i] * wr[i];
        g_rnorm[b * COUT + o] = 1.0f / sqrtf(sum);
    }
}

// ---------------------------------------------------------------------------
// K3: g_wmod[b][ic][k][oc] = conv_w[oc][ic][k] * style[b][ic] * rnorm[b][oc]
// ---------------------------------------------------------------------------
__global__ void wmod_kernel(const float* __restrict__ conv_w) {
    size_t idx = (size_t)blockIdx.x * blockDim.x + threadIdx.x;
    if (idx >= (size_t)BB * CIN * 9 * COUT) return;
    int oc = (int)(idx & 511);
    size_t r = idx >> 9;
    int k = (int)(r % 9);
    size_t r2 = r / 9;
    int ic = (int)(r2 & 511);
    int b  = (int)(r2 >> 9);
    float w = conv_w[((size_t)oc * CIN + ic) * 9 + k];
    g_wmod[idx] = w * g_style[b * CIN + ic] * g_rnorm[b * COUT + oc];
}

// ---------------------------------------------------------------------------
// Conv kernel: per CTA: one b, 64 output channels, 4 output rows x 64 cols.
// Threads (256): oc_g = t>>5 (8 groups of 8 oc), px = t&31 -> (row = px>>3,
// col0 = (px&7)*8). Each thread: 8 oc x 8 px register tile.
// ---------------------------------------------------------------------------
__global__ void __launch_bounds__(256)
conv_kernel(const float* __restrict__ imgs,
            const float* __restrict__ noise,
            const float* __restrict__ conv_b,
            const float* __restrict__ nwp,
            float* __restrict__ out) {
    __shared__ float sx[8][6][66];   // [ic_local][row(-1..+4)][col(-1..64)]
    __shared__ float sw[8][9][64];   // [ic_local][ky*3+kx][oc within tile]

    const int b   = blockIdx.z;
    const int oct = blockIdx.y;            // 0..7, 64-oc tile
    const int h0  = blockIdx.x * 4;        // 0..60 step 4
    const int t   = threadIdx.x;
    const int oc_g = t >> 5;               // 0..7
    const int px   = t & 31;
    const int row  = px >> 3;              // 0..3
    const int col0 = (px & 7) << 3;        // 0..56 step 8

    float acc[8][8];
    #pragma unroll
    for (int j = 0; j < 8; j++)
        #pragma unroll
        for (int p = 0; p < 8; p++) acc[j][p] = 0.f;

    const float* imgb = imgs + (size_t)b * CIN * HH * WW;

    for (int ic0 = 0; ic0 < CIN; ic0 += 8) {
        // stage input (with halo, zero padded)
        for (int idx = t; idx < 8 * 6 * 66; idx += 256) {
            int icl = idx / 396;
            int rem = idx - icl * 396;
            int r = rem / 66;
            int c = rem - r * 66;
            int gh = h0 - 1 + r;
            int gw = c - 1;
            float v = 0.f;
            if ((unsigned)gh < (unsigned)HH && (unsigned)gw < (unsigned)WW)
                v = imgb[((size_t)(ic0 + icl) * HH + gh) * WW + gw];
            sx[icl][r][c] = v;
        }
        // stage weights (coalesced over oc)
        {
            const float* wp = g_wmod + (((size_t)b * CIN + ic0) * 9) * COUT + oct * 64;
            for (int idx = t; idx < 8 * 9 * 64; idx += 256) {
                int icl = idx / 576;
                int rem = idx - icl * 576;
                int k = rem >> 6;
                int oc = rem & 63;
                sw[icl][k][oc] = wp[((size_t)icl * 9 + k) * COUT + oc];
            }
        }
        __syncthreads();

        #pragma unroll 1
        for (int icl = 0; icl < 8; icl++) {
            #pragma unroll
            for (int ky = 0; ky < 3; ky++) {
                float xv[10];
                #pragma unroll
                for (int j = 0; j < 10; j++)
                    xv[j] = sx[icl][row + ky][col0 + j];
                #pragma unroll
                for (int kx = 0; kx < 3; kx++) {
                    float wv[8];
                    #pragma unroll
                    for (int j = 0; j < 8; j++)
                        wv[j] = sw[icl][ky * 3 + kx][oc_g * 8 + j];
                    #pragma unroll
                    for (int j = 0; j < 8; j++)
                        #pragma unroll
                        for (int p = 0; p < 8; p++)
                            acc[j][p] += wv[j] * xv[p + kx];
                }
            }
        }
        __syncthreads();
    }

    // epilogue: bias + noise + LeakyReLU(0.2)
    const float nw = nwp[0];
    const int h = h0 + row;
    const float* np = noise + ((size_t)b * HH + h) * WW + col0;
    float nz[8];
    #pragma unroll
    for (int p = 0; p < 8; p++) nz[p] = np[p] * nw;

    #pragma unroll
    for (int j = 0; j < 8; j++) {
        int o = oct * 64 + oc_g * 8 + j;
        float bias = conv_b[o];
        float* op = out + (((size_t)b * COUT + o) * HH + h) * WW + col0;
        #pragma unroll
        for (int p = 0; p < 8; p++) {
            float v = acc[j][p] + bias + nz[p];
            op[p] = (v >= 0.f) ? v : 0.2f * v;
        }
    }
}

// ---------------------------------------------------------------------------
extern "C" void kernel_launch(void* const* d_in, const int* in_sizes, int n_in,
                              void* d_out, int out_size) {
    const float* imgs    = (const float*)d_in[0];
    const float* w_embs  = (const float*)d_in[1];
    const float* noise   = (const float*)d_in[2];
    const float* conv_w  = (const float*)d_in[3];
    const float* conv_b  = (const float*)d_in[4];
    const float* style_w = (const float*)d_in[5];
    const float* style_b = (const float*)d_in[6];
    const float* nwp     = (const float*)d_in[7];
    float* out = (float*)d_out;

    style_kernel<<<BB, 512>>>(w_embs, style_w, style_b);
    wsumsq_kernel<<<(COUT * CIN + 255) / 256, 256>>>(conv_w);
    rnorm_kernel<<<BB, 512>>>();
    {
        size_t n = (size_t)BB * CIN * 9 * COUT;
        wmod_kernel<<<(unsigned)((n + 255) / 256), 256>>>(conv_w);
    }
    {
        dim3 grid(HH / 4, COUT / 64, BB);   // (16, 8, 16)
        conv_kernel<<<grid, 256>>>(imgs, noise, conv_b, nwp, out);
    }
}

// round 2
// speedup vs baseline: 1.6695x; 1.6695x over previous
#include <cuda_runtime.h>
#include <cstdint>

#define BB   16
#define CIN  512
#define COUT 512
#define HH   64
#define WW   64
#define WDIM 512

// Scratch (static device arrays — no allocation in kernel_launch)
__device__ float g_style[BB * CIN];            // style[b][i]
__device__ float g_wsumsq[COUT * CIN];         // sum over 3x3 of conv_w^2, [o][i]
__device__ float g_rnorm[BB * COUT];           // 1/norm per (b,o)
__device__ float g_wmod[(size_t)BB * CIN * 9 * COUT];  // [b][ic][k][oc], oc fastest (tf32-rounded)

__device__ __forceinline__ float tf32r(float x) {
    uint32_t u;
    asm("cvt.rna.tf32.f32 %0, %1;" : "=r"(u) : "f"(x));
    return __uint_as_float(u);
}

__device__ __forceinline__ void mma_tf32(float& c0, float& c1, float& c2, float& c3,
                                         uint32_t a0, uint32_t a1, uint32_t a2, uint32_t a3,
                                         uint32_t b0, uint32_t b1) {
    asm volatile(
        "mma.sync.aligned.m16n8k8.row.col.f32.tf32.tf32.f32 "
        "{%0,%1,%2,%3}, {%4,%5,%6,%7}, {%8,%9}, {%0,%1,%2,%3};"
        : "+f"(c0), "+f"(c1), "+f"(c2), "+f"(c3)
        : "r"(a0), "r"(a1), "r"(a2), "r"(a3), "r"(b0), "r"(b1));
}

// ---------------------------------------------------------------------------
// K1: style[b][i] = dot(w_embs[b,:], style_w[i,:]) + style_b[i] + 1
// ---------------------------------------------------------------------------
__global__ void style_kernel(const float* __restrict__ w_embs,
                             const float* __restrict__ style_w,
                             const float* __restrict__ style_b) {
    __shared__ float se[WDIM];
    int b = blockIdx.x;
    for (int k = threadIdx.x; k < WDIM; k += blockDim.x)
        se[k] = w_embs[b * WDIM + k];
    __syncthreads();
    for (int i = threadIdx.x; i < CIN; i += blockDim.x) {
        const float* sr = style_w + (size_t)i * WDIM;
        float s = 0.f;
        #pragma unroll 8
        for (int k = 0; k < WDIM; k++) s += se[k] * sr[k];
        g_style[b * CIN + i] = s + style_b[i] + 1.0f;
    }
}

// ---------------------------------------------------------------------------
// K2a: wsumsq[o][i] = sum_{k in 3x3} conv_w[o][i][k]^2
// ---------------------------------------------------------------------------
__global__ void wsumsq_kernel(const float* __restrict__ conv_w) {
    int idx = blockIdx.x * blockDim.x + threadIdx.x;  // o*512 + i
    if (idx < COUT * CIN) {
        const float* p = conv_w + (size_t)idx * 9;
        float s = 0.f;
        #pragma unroll
        for (int k = 0; k < 9; k++) s += p[k] * p[k];
        g_wsumsq[idx] = s;
    }
}

// ---------------------------------------------------------------------------
// K2b: rnorm[b][o] = 1/sqrt(sum_i style[b,i]^2 * wsumsq[o][i])
// ---------------------------------------------------------------------------
__global__ void rnorm_kernel() {
    __shared__ float s2[CIN];
    int b = blockIdx.x;
    for (int i = threadIdx.x; i < CIN; i += blockDim.x) {
        float s = g_style[b * CIN + i];
        s2[i] = s * s;
    }
    __syncthreads();
    for (int o = threadIdx.x; o < COUT; o += blockDim.x) {
        const float* wr = g_wsumsq + (size_t)o * CIN;
        float sum = 0.f;
        #pragma unroll 8
        for (int i = 0; i < CIN; i++) sum += s2[i] * wr[i];
        g_rnorm[b * COUT + o] = 1.0f / sqrtf(sum);
    }
}

// ---------------------------------------------------------------------------
// K3 (tiled, coalesced): g_wmod[b][ic][k][oc] =
//     tf32_round( conv_w[oc][ic][k] * style[b][ic] * rnorm[b][oc] )
// CTA = 8 ic x 64 oc block; smem-transposed read of conv_w.
// ---------------------------------------------------------------------------
__global__ void __launch_bounds__(256)
wmod_kernel(const float* __restrict__ conv_w) {
    __shared__ float sblk[64 * 73];   // [oc_l][ic_l*9+k], pad 73 (9*oc mod 32 distinct)
    __shared__ float ssty[16 * 8];    // [b][ic_l]
    __shared__ float srn[16 * 64];    // [b][oc_l]

    const int ic0 = blockIdx.x * 8;
    const int oc0 = blockIdx.y * 64;
    const int t = threadIdx.x;

    for (int idx = t; idx < 64 * 72; idx += 256) {
        int oc_l = idx / 72;
        int j = idx - oc_l * 72;
        sblk[oc_l * 73 + j] = conv_w[(size_t)(oc0 + oc_l) * (CIN * 9) + ic0 * 9 + j];
    }
    for (int idx = t; idx < 16 * 8; idx += 256) {
        int b = idx >> 3, icl = idx & 7;
        ssty[idx] = g_style[b * CIN + ic0 + icl];
    }
    for (int idx = t; idx < 16 * 64; idx += 256) {
        int b = idx >> 6, oc = idx & 63;
        srn[idx] = g_rnorm[b * COUT + oc0 + oc];
    }
    __syncthreads();

    for (int b = 0; b < BB; b++) {
        for (int idx = t; idx < 8 * 9 * 64; idx += 256) {
            int icl = idx / 576;
            int rem = idx - icl * 576;
            int k = rem >> 6;
            int oc = rem & 63;
            float v = sblk[oc * 73 + icl * 9 + k] * ssty[b * 8 + icl] * srn[b * 64 + oc];
            g_wmod[(((size_t)(b * CIN + ic0 + icl) * 9) + k) * COUT + oc0 + oc] = tf32r(v);
        }
    }
}

// ---------------------------------------------------------------------------
// Conv via mma.sync.m16n8k8.tf32 (implicit GEMM).
// CTA: 256 thr = 8 warps; tile = 128 oc x (4 rows x 64 cols).
// Warp (w): oc_half = w>>2 (64 oc), row = w&3 (one full 64-col row).
// Warp tile: 64 oc x 64 px -> 4 M-frags x 8 N-frags.
// K staged 8 ic at a time; 9 taps = shifted smem views.
// ---------------------------------------------------------------------------
#define SX(ic, r, c) sx[(ic) * 408 + (r) * 68 + (c)]
#define SWT(tp, ic, oc) sw[(tp) * 1088 + (ic) * 136 + (oc)]

__global__ void __launch_bounds__(256, 1)
conv_mma_kernel(const float* __restrict__ imgs,
                const float* __restrict__ noise,
                const float* __restrict__ conv_b,
                const float* __restrict__ nwp,
                float* __restrict__ out) {
    extern __shared__ float smem[];
    float* sx = smem;            // 8 ic x 6 rows x 68 (66 used)  = 3264 f
    float* sw = smem + 3264;     // 9 tap x 8 ic x 136 (128 used) = 9792 f

    const int b = blockIdx.z;
    const int oct = blockIdx.y;            // 0..3 -> 128-oc tile
    const int h0 = blockIdx.x * 4;         // 0..60
    const int t = threadIdx.x;
    const int warp = t >> 5;
    const int lane = t & 31;
    const int g = lane >> 2;               // 0..7
    const int tg = lane & 3;               // 0..3
    const int oc_half = warp >> 2;         // 0..1
    const int row = warp & 3;              // 0..3

    float c[4][8][4];
    #pragma unroll
    for (int mf = 0; mf < 4; mf++)
        #pragma unroll
        for (int nf = 0; nf < 8; nf++)
            #pragma unroll
            for (int q = 0; q < 4; q++) c[mf][nf][q] = 0.f;

    const float* imgb = imgs + (size_t)b * CIN * HH * WW;
    const float* wpb = g_wmod + ((size_t)b * CIN) * 9 * COUT + oct * 128;

    for (int ic0 = 0; ic0 < CIN; ic0 += 8) {
        // --- stage input (tf32-rounded, zero halo) ---
        for (int idx = t; idx < 8 * 6 * 66; idx += 256) {
            int icl = idx / 396;
            int rem = idx - icl * 396;
            int r = rem / 66;
            int cc = rem - r * 66;
            int gh = h0 - 1 + r;
            int gw = cc - 1;
            float v = 0.f;
            if ((unsigned)gh < (unsigned)HH && (unsigned)gw < (unsigned)WW)
                v = imgb[((size_t)(ic0 + icl) * HH + gh) * WW + gw];
            SX(icl, r, cc) = tf32r(v);
        }
        // --- stage weights (already tf32-rounded) ---
        {
            const float* wp = wpb + (size_t)ic0 * 9 * COUT;
            for (int idx = t; idx < 8 * 9 * 128; idx += 256) {
                int icl = idx / 1152;
                int rem = idx - icl * 1152;
                int k = rem >> 7;
                int oc = rem & 127;
                SWT(k, icl, oc) = wp[((size_t)icl * 9 + k) * COUT + oc];
            }
        }
        __syncthreads();

        #pragma unroll
        for (int ky = 0; ky < 3; ky++) {
            #pragma unroll
            for (int kx = 0; kx < 3; kx++) {
                const int tap = ky * 3 + kx;
                uint32_t a[4][4];
                #pragma unroll
                for (int mf = 0; mf < 4; mf++) {
                    int boc = oc_half * 64 + mf * 16 + g;
                    a[mf][0] = __float_as_uint(SWT(tap, tg, boc));
                    a[mf][1] = __float_as_uint(SWT(tap, tg, boc + 8));
                    a[mf][2] = __float_as_uint(SWT(tap, tg + 4, boc));
                    a[mf][3] = __float_as_uint(SWT(tap, tg + 4, boc + 8));
                }
                const int rr = row + ky;
                #pragma unroll
                for (int nf = 0; nf < 8; nf++) {
                    int col = nf * 8 + g + kx;
                    uint32_t b0 = __float_as_uint(SX(tg, rr, col));
                    uint32_t b1 = __float_as_uint(SX(tg + 4, rr, col));
                    #pragma unroll
                    for (int mf = 0; mf < 4; mf++)
                        mma_tf32(c[mf][nf][0], c[mf][nf][1], c[mf][nf][2], c[mf][nf][3],
                                 a[mf][0], a[mf][1], a[mf][2], a[mf][3], b0, b1);
                }
            }
        }
        __syncthreads();
    }

    // --- epilogue: bias + noise + LeakyReLU(0.2) ---
    const float nw = nwp[0];
    const int h = h0 + row;
    float2 nz[8];
    #pragma unroll
    for (int nf = 0; nf < 8; nf++) {
        int w = nf * 8 + 2 * tg;
        nz[nf] = *(const float2*)(noise + ((size_t)b * HH + h) * WW + w);
        nz[nf].x *= nw;
        nz[nf].y *= nw;
    }
    #pragma unroll
    for (int mf = 0; mf < 4; mf++) {
        #pragma unroll
        for (int part = 0; part < 2; part++) {
            int oc = oct * 128 + oc_half * 64 + mf * 16 + g + part * 8;
            float bias = conv_b[oc];
            float* op = out + (((size_t)b * COUT + oc) * HH + h) * WW;
            #pragma unroll
            for (int nf = 0; nf < 8; nf++) {
                int w = nf * 8 + 2 * tg;
                float v0 = c[mf][nf][part * 2 + 0] + bias + nz[nf].x;
                float v1 = c[mf][nf][part * 2 + 1] + bias + nz[nf].y;
                v0 = (v0 >= 0.f) ? v0 : 0.2f * v0;
                v1 = (v1 >= 0.f) ? v1 : 0.2f * v1;
                *(float2*)(op + w) = make_float2(v0, v1);
            }
        }
    }
}

// ---------------------------------------------------------------------------
extern "C" void kernel_launch(void* const* d_in, const int* in_sizes, int n_in,
                              void* d_out, int out_size) {
    const float* imgs    = (const float*)d_in[0];
    const float* w_embs  = (const float*)d_in[1];
    const float* noise   = (const float*)d_in[2];
    const float* conv_w  = (const float*)d_in[3];
    const float* conv_b  = (const float*)d_in[4];
    const float* style_w = (const float*)d_in[5];
    const float* style_b = (const float*)d_in[6];
    const float* nwp     = (const float*)d_in[7];
    float* out = (float*)d_out;

    style_kernel<<<BB, 512>>>(w_embs, style_w, style_b);
    wsumsq_kernel<<<(COUT * CIN + 255) / 256, 256>>>(conv_w);
    rnorm_kernel<<<BB, 512>>>();
    {
        dim3 grid(CIN / 8, COUT / 64);   // (64, 8)
        wmod_kernel<<<grid, 256>>>(conv_w);
    }
    {
        const int smem_bytes = (3264 + 9792) * 4;   // 52224 B
        cudaFuncSetAttribute(conv_mma_kernel,
                             cudaFuncAttributeMaxDynamicSharedMemorySize, smem_bytes);
        dim3 grid(HH / 4, COUT / 128, BB);   // (16, 4, 16)
        conv_mma_kernel<<<grid, 256, smem_bytes>>>(imgs, noise, conv_b, nwp, out);
    }
}

// round 3
// speedup vs baseline: 1.6733x; 1.0023x over previous
#include <cuda_runtime.h>
#include <cstdint>

#define BB   16
#define CIN  512
#define COUT 512
#define HH   64
#define WW   64
#define WDIM 512

// Scratch (static device arrays — no allocation in kernel_launch)
__device__ float g_style[BB * CIN];            // style[b][i]
__device__ float g_wsumsq[COUT * CIN];         // sum over 3x3 of conv_w^2, [o][i]
__device__ float g_rnorm[BB * COUT];           // 1/norm per (b,o)
__device__ float g_wmod[(size_t)BB * CIN * 9 * COUT];  // [b][ic][k][oc], oc fastest (tf32-rounded)

__device__ __forceinline__ float tf32r(float x) {
    uint32_t u;
    asm("cvt.rna.tf32.f32 %0, %1;" : "=r"(u) : "f"(x));
    return __uint_as_float(u);
}

__device__ __forceinline__ void mma_tf32(float& c0, float& c1, float& c2, float& c3,
                                         uint32_t a0, uint32_t a1, uint32_t a2, uint32_t a3,
                                         uint32_t b0, uint32_t b1) {
    asm volatile(
        "mma.sync.aligned.m16n8k8.row.col.f32.tf32.tf32.f32 "
        "{%0,%1,%2,%3}, {%4,%5,%6,%7}, {%8,%9}, {%0,%1,%2,%3};"
        : "+f"(c0), "+f"(c1), "+f"(c2), "+f"(c3)
        : "r"(a0), "r"(a1), "r"(a2), "r"(a3), "r"(b0), "r"(b1));
}

// ---------------------------------------------------------------------------
// K1: style[b][i] = dot(w_embs[b,:], style_w[i,:]) + style_b[i] + 1
// ---------------------------------------------------------------------------
__global__ void style_kernel(const float* __restrict__ w_embs,
                             const float* __restrict__ style_w,
                             const float* __restrict__ style_b) {
    __shared__ float se[WDIM];
    int b = blockIdx.x;
    for (int k = threadIdx.x; k < WDIM; k += blockDim.x)
        se[k] = w_embs[b * WDIM + k];
    __syncthreads();
    for (int i = threadIdx.x; i < CIN; i += blockDim.x) {
        const float* sr = style_w + (size_t)i * WDIM;
        float s = 0.f;
        #pragma unroll 8
        for (int k = 0; k < WDIM; k++) s += se[k] * sr[k];
        g_style[b * CIN + i] = s + style_b[i] + 1.0f;
    }
}

// ---------------------------------------------------------------------------
// K2a: wsumsq[o][i] = sum_{k in 3x3} conv_w[o][i][k]^2
// ---------------------------------------------------------------------------
__global__ void wsumsq_kernel(const float* __restrict__ conv_w) {
    int idx = blockIdx.x * blockDim.x + threadIdx.x;  // o*512 + i
    if (idx < COUT * CIN) {
        const float* p = conv_w + (size_t)idx * 9;
        float s = 0.f;
        #pragma unroll
        for (int k = 0; k < 9; k++) s += p[k] * p[k];
        g_wsumsq[idx] = s;
    }
}

// ---------------------------------------------------------------------------
// K2b: rnorm[b][o] = 1/sqrt(sum_i style[b,i]^2 * wsumsq[o][i])
// ---------------------------------------------------------------------------
__global__ void rnorm_kernel() {
    __shared__ float s2[CIN];
    int b = blockIdx.x;
    for (int i = threadIdx.x; i < CIN; i += blockDim.x) {
        float s = g_style[b * CIN + i];
        s2[i] = s * s;
    }
    __syncthreads();
    for (int o = threadIdx.x; o < COUT; o += blockDim.x) {
        const float* wr = g_wsumsq + (size_t)o * CIN;
        float sum = 0.f;
        #pragma unroll 8
        for (int i = 0; i < CIN; i++) sum += s2[i] * wr[i];
        g_rnorm[b * COUT + o] = 1.0f / sqrtf(sum);
    }
}

// ---------------------------------------------------------------------------
// K3 (tiled, coalesced): g_wmod[b][ic][k][oc] =
//     tf32_round( conv_w[oc][ic][k] * style[b][ic] * rnorm[b][oc] )
// CTA = 8 ic x 64 oc block; smem-transposed read of conv_w.
// ---------------------------------------------------------------------------
__global__ void __launch_bounds__(256)
wmod_kernel(const float* __restrict__ conv_w) {
    __shared__ float sblk[64 * 73];   // [oc_l][ic_l*9+k], pad 73 (9*oc mod 32 distinct)
    __shared__ float ssty[16 * 8];    // [b][ic_l]
    __shared__ float srn[16 * 64];    // [b][oc_l]

    const int ic0 = blockIdx.x * 8;
    const int oc0 = blockIdx.y * 64;
    const int t = threadIdx.x;

    for (int idx = t; idx < 64 * 72; idx += 256) {
        int oc_l = idx / 72;
        int j = idx - oc_l * 72;
        sblk[oc_l * 73 + j] = conv_w[(size_t)(oc0 + oc_l) * (CIN * 9) + ic0 * 9 + j];
    }
    for (int idx = t; idx < 16 * 8; idx += 256) {
        int b = idx >> 3, icl = idx & 7;
        ssty[idx] = g_style[b * CIN + ic0 + icl];
    }
    for (int idx = t; idx < 16 * 64; idx += 256) {
        int b = idx >> 6, oc = idx & 63;
        srn[idx] = g_rnorm[b * COUT + oc0 + oc];
    }
    __syncthreads();

    for (int b = 0; b < BB; b++) {
        for (int idx = t; idx < 8 * 9 * 64; idx += 256) {
            int icl = idx / 576;
            int rem = idx - icl * 576;
            int k = rem >> 6;
            int oc = rem & 63;
            float v = sblk[oc * 73 + icl * 9 + k] * ssty[b * 8 + icl] * srn[b * 64 + oc];
            g_wmod[(((size_t)(b * CIN + ic0 + icl) * 9) + k) * COUT + oc0 + oc] = tf32r(v);
        }
    }
}

// ---------------------------------------------------------------------------
// Conv via mma.sync.m16n8k8.tf32 (implicit GEMM).
// CTA: 256 thr = 8 warps; tile = 128 oc x (4 rows x 64 cols).
// Warp (w): oc_half = w>>2 (64 oc), row = w&3 (one full 64-col row).
// Warp tile: 64 oc x 64 px -> 4 M-frags x 8 N-frags.
// K staged 8 ic at a time; 9 taps = shifted smem views.
// ---------------------------------------------------------------------------
#define SX(ic, r, c) sx[(ic) * 408 + (r) * 68 + (c)]
#define SWT(tp, ic, oc) sw[(tp) * 1088 + (ic) * 136 + (oc)]

__global__ void __launch_bounds__(256, 1)
conv_mma_kernel(const float* __restrict__ imgs,
                const float* __restrict__ noise,
                const float* __restrict__ conv_b,
                const float* __restrict__ nwp,
                float* __restrict__ out) {
    extern __shared__ float smem[];
    float* sx = smem;            // 8 ic x 6 rows x 68 (66 used)  = 3264 f
    float* sw = smem + 3264;     // 9 tap x 8 ic x 136 (128 used) = 9792 f

    const int b = blockIdx.z;
    const int oct = blockIdx.y;            // 0..3 -> 128-oc tile
    const int h0 = blockIdx.x * 4;         // 0..60
    const int t = threadIdx.x;
    const int warp = t >> 5;
    const int lane = t & 31;
    const int g = lane >> 2;               // 0..7
    const int tg = lane & 3;               // 0..3
    const int oc_half = warp >> 2;         // 0..1
    const int row = warp & 3;              // 0..3

    float c[4][8][4];
    #pragma unroll
    for (int mf = 0; mf < 4; mf++)
        #pragma unroll
        for (int nf = 0; nf < 8; nf++)
            #pragma unroll
            for (int q = 0; q < 4; q++) c[mf][nf][q] = 0.f;

    const float* imgb = imgs + (size_t)b * CIN * HH * WW;
    const float* wpb = g_wmod + ((size_t)b * CIN) * 9 * COUT + oct * 128;

    for (int ic0 = 0; ic0 < CIN; ic0 += 8) {
        // --- stage input (tf32-rounded, zero halo) ---
        for (int idx = t; idx < 8 * 6 * 66; idx += 256) {
            int icl = idx / 396;
            int rem = idx - icl * 396;
            int r = rem / 66;
            int cc = rem - r * 66;
            int gh = h0 - 1 + r;
            int gw = cc - 1;
            float v = 0.f;
            if ((unsigned)gh < (unsigned)HH && (unsigned)gw < (unsigned)WW)
                v = imgb[((size_t)(ic0 + icl) * HH + gh) * WW + gw];
            SX(icl, r, cc) = tf32r(v);
        }
        // --- stage weights (already tf32-rounded) ---
        {
            const float* wp = wpb + (size_t)ic0 * 9 * COUT;
            for (int idx = t; idx < 8 * 9 * 128; idx += 256) {
                int icl = idx / 1152;
                int rem = idx - icl * 1152;
                int k = rem >> 7;
                int oc = rem & 127;
                SWT(k, icl, oc) = wp[((size_t)icl * 9 + k) * COUT + oc];
            }
        }
        __syncthreads();

        #pragma unroll
        for (int ky = 0; ky < 3; ky++) {
            #pragma unroll
            for (int kx = 0; kx < 3; kx++) {
                const int tap = ky * 3 + kx;
                uint32_t a[4][4];
                #pragma unroll
                for (int mf = 0; mf < 4; mf++) {
                    int boc = oc_half * 64 + mf * 16 + g;
                    a[mf][0] = __float_as_uint(SWT(tap, tg, boc));
                    a[mf][1] = __float_as_uint(SWT(tap, tg, boc + 8));
                    a[mf][2] = __float_as_uint(SWT(tap, tg + 4, boc));
                    a[mf][3] = __float_as_uint(SWT(tap, tg + 4, boc + 8));
                }
                const int rr = row + ky;
                #pragma unroll
                for (int nf = 0; nf < 8; nf++) {
                    int col = nf * 8 + g + kx;
                    uint32_t b0 = __float_as_uint(SX(tg, rr, col));
                    uint32_t b1 = __float_as_uint(SX(tg + 4, rr, col));
                    #pragma unroll
                    for (int mf = 0; mf < 4; mf++)
                        mma_tf32(c[mf][nf][0], c[mf][nf][1], c[mf][nf][2], c[mf][nf][3],
                                 a[mf][0], a[mf][1], a[mf][2], a[mf][3], b0, b1);
                }
            }
        }
        __syncthreads();
    }

    // --- epilogue: bias + noise + LeakyReLU(0.2) ---
    const float nw = nwp[0];
    const int h = h0 + row;
    float2 nz[8];
    #pragma unroll
    for (int nf = 0; nf < 8; nf++) {
        int w = nf * 8 + 2 * tg;
        nz[nf] = *(const float2*)(noise + ((size_t)b * HH + h) * WW + w);
        nz[nf].x *= nw;
        nz[nf].y *= nw;
    }
    #pragma unroll
    for (int mf = 0; mf < 4; mf++) {
        #pragma unroll
        for (int part = 0; part < 2; part++) {
            int oc = oct * 128 + oc_half * 64 + mf * 16 + g + part * 8;
            float bias = conv_b[oc];
            float* op = out + (((size_t)b * COUT + oc) * HH + h) * WW;
            #pragma unroll
            for (int nf = 0; nf < 8; nf++) {
                int w = nf * 8 + 2 * tg;
                float v0 = c[mf][nf][part * 2 + 0] + bias + nz[nf].x;
                float v1 = c[mf][nf][part * 2 + 1] + bias + nz[nf].y;
                v0 = (v0 >= 0.f) ? v0 : 0.2f * v0;
                v1 = (v1 >= 0.f) ? v1 : 0.2f * v1;
                *(float2*)(op + w) = make_float2(v0, v1);
            }
        }
    }
}

// ---------------------------------------------------------------------------
extern "C" void kernel_launch(void* const* d_in, const int* in_sizes, int n_in,
                              void* d_out, int out_size) {
    const float* imgs    = (const float*)d_in[0];
    const float* w_embs  = (const float*)d_in[1];
    const float* noise   = (const float*)d_in[2];
    const float* conv_w  = (const float*)d_in[3];
    const float* conv_b  = (const float*)d_in[4];
    const float* style_w = (const float*)d_in[5];
    const float* style_b = (const float*)d_in[6];
    const float* nwp     = (const float*)d_in[7];
    float* out = (float*)d_out;

    style_kernel<<<BB, 512>>>(w_embs, style_w, style_b);
    wsumsq_kernel<<<(COUT * CIN + 255) / 256, 256>>>(conv_w);
    rnorm_kernel<<<BB, 512>>>();
    {
        dim3 grid(CIN / 8, COUT / 64);   // (64, 8)
        wmod_kernel<<<grid, 256>>>(conv_w);
    }
    {
        const int smem_bytes = (3264 + 9792) * 4;   // 52224 B
        cudaFuncSetAttribute(conv_mma_kernel,
                             cudaFuncAttributeMaxDynamicSharedMemorySize, smem_bytes);
        dim3 grid(HH / 4, COUT / 128, BB);   // (16, 4, 16)
        conv_mma_kernel<<<grid, 256, smem_bytes>>>(imgs, noise, conv_b, nwp, out);
    }
}